// round 12
// baseline (speedup 1.0000x reference)
#include <cuda_runtime.h>
#include <cuda_fp16.h>
#include <math.h>
#include <stdint.h>

// Problem dims (fixed by reference)
#define DIM    1024
#define SEQ    2048
#define BATCH  2
#define NTOK   4096     // BATCH*SEQ
#define NHEAD  16
#define HD     64
#define FF     4096

// ---------------- scratch (static device globals; no allocs allowed) ----------------
__device__ __half g_xn  [NTOK * DIM];   // LN1 output (fp16)
__device__ __half g_q   [NTOK * DIM];   // [B,H,S,hd] fp16 (pre-scaled by 0.125*log2e)
__device__ __half g_k   [NTOK * DIM];
__device__ __half g_v   [NTOK * DIM];
__device__ __half g_ctx [NTOK * DIM];   // attention output fp16
__device__ float  g_res1[NTOK * DIM];   // attn_out + x (fp32)
__device__ __half g_xn2 [NTOK * DIM];   // LN2 output fp16
__device__ __half g_h1  [NTOK * FF];    // gelu(...) fp16
__device__ __half g_wh  [12 * 1024 * 1024];  // fp16 weights: wq|wk|wv|wo|w1|w2

// ---------------- PTX helpers ----------------
__device__ __forceinline__ uint32_t smem_u32(const void* p) {
    uint32_t a;
    asm("{ .reg .u64 t; cvta.to.shared.u64 t, %1; cvt.u32.u64 %0, t; }" : "=r"(a) : "l"(p));
    return a;
}
__device__ __forceinline__ void cp_async16(uint32_t dst, const void* src) {
    asm volatile("cp.async.cg.shared.global [%0], [%1], 16;" :: "r"(dst), "l"(src));
}
#define CP_COMMIT() asm volatile("cp.async.commit_group;" ::: "memory")
#define CP_WAIT(n)  asm volatile("cp.async.wait_group %0;" :: "n"(n) : "memory")

__device__ __forceinline__ void ldsm4(uint32_t* r, uint32_t addr) {
    asm volatile("ldmatrix.sync.aligned.m8n8.x4.shared.b16 {%0,%1,%2,%3}, [%4];"
        : "=r"(r[0]), "=r"(r[1]), "=r"(r[2]), "=r"(r[3]) : "r"(addr));
}
__device__ __forceinline__ void ldsm4t(uint32_t* r, uint32_t addr) {
    asm volatile("ldmatrix.sync.aligned.m8n8.x4.trans.shared.b16 {%0,%1,%2,%3}, [%4];"
        : "=r"(r[0]), "=r"(r[1]), "=r"(r[2]), "=r"(r[3]) : "r"(addr));
}
__device__ __forceinline__ void mma_f16(float* d, const uint32_t* a, uint32_t b0, uint32_t b1) {
    asm volatile("mma.sync.aligned.m16n8k16.row.col.f32.f16.f16.f32 "
                 "{%0,%1,%2,%3}, {%4,%5,%6,%7}, {%8,%9}, {%0,%1,%2,%3};"
                 : "+f"(d[0]), "+f"(d[1]), "+f"(d[2]), "+f"(d[3])
                 : "r"(a[0]), "r"(a[1]), "r"(a[2]), "r"(a[3]), "r"(b0), "r"(b1));
}
__device__ __forceinline__ uint32_t sw128(uint32_t off) {
    return off ^ ((off >> 3) & 0x70);
}
__device__ __forceinline__ uint32_t pack_h2(float x, float y) {
    __half2 h = __floats2half2_rn(x, y);
    return *(uint32_t*)&h;
}

// ---------------- weight fp16 conversion (single launch) ----------------
__global__ void cvt_all(const float4* __restrict__ wq, const float4* __restrict__ wk,
                        const float4* __restrict__ wv, const float4* __restrict__ wo,
                        const float4* __restrict__ w1, const float4* __restrict__ w2,
                        __half2* __restrict__ dst)
{
    int i = blockIdx.x * 256 + threadIdx.x;   // float4 index, 0..3145727
    const float4* s;
    int j;
    if (i < 1048576) {
        int seg = i >> 18;
        j = i & 262143;
        s = (seg == 0) ? wq : (seg == 1) ? wk : (seg == 2) ? wv : wo;
    } else if (i < 2097152) {
        s = w1; j = i - 1048576;
    } else {
        s = w2; j = i - 2097152;
    }
    float4 v = s[j];
    dst[i * 2]     = __floats2half2_rn(v.x, v.y);
    dst[i * 2 + 1] = __floats2half2_rn(v.z, v.w);
}

// ---------------- LayerNorm (ddof=1), fp16 output ----------------
__global__ void ln_kernel(const float* __restrict__ x,
                          const float* __restrict__ scale,
                          const float* __restrict__ shift,
                          __half* __restrict__ out)
{
    int row = blockIdx.x;
    int t   = threadIdx.x;
    const float4* xr = (const float4*)(x + (size_t)row * DIM);
    float4 v = xr[t];
    float s  = v.x + v.y + v.z + v.w;
    float sq = v.x*v.x + v.y*v.y + v.z*v.z + v.w*v.w;
    #pragma unroll
    for (int o = 16; o > 0; o >>= 1) {
        s  += __shfl_xor_sync(0xffffffffu, s,  o);
        sq += __shfl_xor_sync(0xffffffffu, sq, o);
    }
    __shared__ float sbuf[18];
    int w = t >> 5, l = t & 31;
    if (l == 0) { sbuf[w] = s; sbuf[8 + w] = sq; }
    __syncthreads();
    if (t == 0) {
        float ts = 0.f, tq = 0.f;
        #pragma unroll
        for (int i = 0; i < 8; i++) { ts += sbuf[i]; tq += sbuf[8 + i]; }
        float mean = ts * (1.0f / 1024.0f);
        float var  = (tq - 1024.0f * mean * mean) * (1.0f / 1023.0f);
        sbuf[16] = mean;
        sbuf[17] = rsqrtf(var + 1e-5f);
    }
    __syncthreads();
    float mean = sbuf[16], inv = sbuf[17];
    float4 sc = ((const float4*)scale)[t];
    float4 sh = ((const float4*)shift)[t];
    __half2* op = (__half2*)(out + (size_t)row * DIM) + t * 2;
    op[0] = __floats2half2_rn((v.x - mean) * inv * sc.x + sh.x,
                              (v.y - mean) * inv * sc.y + sh.y);
    op[1] = __floats2half2_rn((v.z - mean) * inv * sc.z + sh.z,
                              (v.w - mean) * inv * sc.w + sh.w);
}

// ---------------- fp16 mma GEMM, 128x128 CTA tile, 8 warps, K-chunk 64, 3-stage ----------------
#define EPI_QKV     0
#define EPI_BIASRES 1
#define EPI_GELU    2

__device__ __forceinline__ float gelu_tanh(float x) {
    float t = 0.7978845608028654f * (x + 0.044715f * x * x * x);
    return 0.5f * x * (1.0f + tanhf(t));
}

// smem: A[3] 128 rows x 128B SW128 = 16KB each; B[3] 64 k-rows x 272B pitch = 17408B each
#define SM_A(buf)  ((buf) * 16384)
#define SM_B(buf)  (49152 + (buf) * 17408)
#define SM_BYTES   (49152 + 3 * 17408)   // 101376 B -> 2 CTA/SM

template<int EPI>
__device__ __forceinline__ void epi_store(void* __restrict__ Cv,
                                          const float* __restrict__ bias,
                                          const float* __restrict__ resid,
                                          int N, int r, int c, float v0, float v1,
                                          float oscale)
{
    if (EPI == EPI_QKV) {
        __half* C = (__half*)Cv;
        int b = r >> 11, s = r & 2047;
        int h = c >> 6, d = c & 63;
        __half* dst = C + (((size_t)(b * NHEAD + h) * SEQ) + s) * HD + d;
        *(__half2*)dst = __floats2half2_rn(v0 * oscale, v1 * oscale);
    } else if (EPI == EPI_BIASRES) {
        float* C = (float*)Cv;
        size_t idx = (size_t)r * N + c;
        *(float2*)(C + idx) = make_float2(v0 + bias[c]     + resid[idx],
                                          v1 + bias[c + 1] + resid[idx + 1]);
    } else { // EPI_GELU -> fp16
        __half* C = (__half*)Cv;
        size_t idx = (size_t)r * N + c;
        *(__half2*)(C + idx) = __floats2half2_rn(gelu_tanh(v0 + bias[c]),
                                                 gelu_tanh(v1 + bias[c + 1]));
    }
}

// stage one K-chunk of 64: A 128x64 fp16 SW128, B 64x128 fp16 at 272B pitch
__device__ __forceinline__ void stage_tiles(uint32_t sb, int buf,
    const __half* __restrict__ A, const __half* __restrict__ W,
    int bm, int bn, int ch, int K, int N, int tid)
{
    #pragma unroll
    for (int i = 0; i < 4; i++) {
        int idx = tid + (i << 8);
        int row = idx >> 3, c = idx & 7;
        const void* src = A + (size_t)(bm + row) * K + ch * 64 + c * 8;
        cp_async16(sb + SM_A(buf) + sw128(row * 128 + c * 16), src);
    }
    #pragma unroll
    for (int i = 0; i < 4; i++) {
        int idx = tid + (i << 8);
        int row = idx >> 4, c = idx & 15;
        const void* src = W + (size_t)(ch * 64 + row) * N + bn + c * 8;
        cp_async16(sb + SM_B(buf) + row * 272 + c * 16, src);
    }
}

template<int EPI>
__device__ __forceinline__ void gemm_body(
    const __half* __restrict__ A, const __half* __restrict__ W,
    const float* __restrict__ bias, const float* __restrict__ resid,
    void* __restrict__ C, int N, int K, int bm, int bn,
    uint32_t sb, int tid, float oscale)
{
    int lane = tid & 31, wid = tid >> 5;
    int wm = (wid >> 2) * 64, wn = (wid & 3) * 32;

    float acc[4][4][4];
    #pragma unroll
    for (int i = 0; i < 4; i++)
        #pragma unroll
        for (int j = 0; j < 4; j++)
            #pragma unroll
            for (int q = 0; q < 4; q++) acc[i][j][q] = 0.f;

    int nch = K >> 6;

    stage_tiles(sb, 0, A, W, bm, bn, 0, K, N, tid);
    CP_COMMIT();
    stage_tiles(sb, 1, A, W, bm, bn, 1, K, N, tid);
    CP_COMMIT();

    int buf = 0, bufn = 2;          // bufn = (ch+2) % 3
    int l15 = lane & 15, l16 = (lane >> 4) << 4;
    for (int ch = 0; ch < nch; ch++) {
        if (ch + 1 < nch) { CP_WAIT(1); } else { CP_WAIT(0); }
        __syncthreads();
        if (ch + 2 < nch) {
            stage_tiles(sb, bufn, A, W, bm, bn, ch + 2, K, N, tid);
            CP_COMMIT();
        }

        uint32_t As = sb + SM_A(buf);
        uint32_t Bs = sb + SM_B(buf);
        #pragma unroll
        for (int kk = 0; kk < 64; kk += 16) {
            uint32_t a[4][4];
            #pragma unroll
            for (int mt = 0; mt < 4; mt++) {
                int row = wm + mt * 16 + l15;
                ldsm4(a[mt], As + sw128((uint32_t)(row * 128 + kk * 2 + l16)));
            }
            #pragma unroll
            for (int p = 0; p < 2; p++) {
                uint32_t bb[4];
                ldsm4t(bb, Bs + (uint32_t)((kk + l15) * 272 + (wn + p * 16) * 2 + l16));
                #pragma unroll
                for (int mt = 0; mt < 4; mt++) {
                    mma_f16(acc[mt][2 * p],     a[mt], bb[0], bb[1]);
                    mma_f16(acc[mt][2 * p + 1], a[mt], bb[2], bb[3]);
                }
            }
        }
        buf  = (buf  == 2) ? 0 : buf  + 1;
        bufn = (bufn == 2) ? 0 : bufn + 1;
    }

    #pragma unroll
    for (int mt = 0; mt < 4; mt++) {
        int r0 = bm + wm + mt * 16 + (lane >> 2);
        #pragma unroll
        for (int nt = 0; nt < 4; nt++) {
            int c0 = bn + wn + nt * 8 + ((lane & 3) << 1);
            epi_store<EPI>(C, bias, resid, N, r0,     c0, acc[mt][nt][0], acc[mt][nt][1], oscale);
            epi_store<EPI>(C, bias, resid, N, r0 + 8, c0, acc[mt][nt][2], acc[mt][nt][3], oscale);
        }
    }
}

template<int EPI>
__global__ void __launch_bounds__(256, 2)
mma_gemm(const __half* __restrict__ A, const __half* __restrict__ W,
         const float* __restrict__ bias, const float* __restrict__ resid,
         void* __restrict__ C, int M, int N, int K)
{
    extern __shared__ char smem[];
    uint32_t sb = smem_u32(smem);
    int bm = blockIdx.y * 128, bn = blockIdx.x * 128;
    gemm_body<EPI>(A, W, bias, resid, C, N, K, bm, bn, sb, threadIdx.x, 1.0f);
}

// fused QKV: grid.x = 24 (8 n-tiles x 3 weights); q pre-scaled by 0.125*log2(e)
#define QSCALE 0.18033688011112042f   // (1/8) * log2(e)

__global__ void __launch_bounds__(256, 2)
mma_gemm_qkv(const __half* __restrict__ A, const __half* __restrict__ wqkv,
             __half* __restrict__ q, __half* __restrict__ k, __half* __restrict__ v)
{
    extern __shared__ char smem[];
    uint32_t sb = smem_u32(smem);
    int seg = blockIdx.x >> 3;
    int bn  = (blockIdx.x & 7) * 128;
    int bm  = blockIdx.y * 128;
    const __half* W = wqkv + (size_t)seg * (DIM * DIM);
    __half* C = (seg == 0) ? q : (seg == 1) ? k : v;
    float sc = (seg == 0) ? QSCALE : 1.0f;
    gemm_body<EPI_QKV>(A, W, nullptr, nullptr, C, DIM, DIM, bm, bn, sb, threadIdx.x, sc);
}

// ---------------- fp16 mma flash attention (register P, exp2-domain softmax) ----------------
// 1 CTA = 64 q rows of one (b,h); 4 warps; Bc=64, double-buffered K/V.
// Q/K: 64 rows x 128B SW128 (8KB each). V: 64 rows x 144B pitch (9216B each). No P smem.
#define ATT_QS      0
#define ATT_KS(b)   (8192 + (b) * 8192)
#define ATT_VS(b)   (24576 + (b) * 9216)
#define ATT_BYTES   43008

__global__ void __launch_bounds__(128, 4)
fa_kernel(const __half* __restrict__ Q, const __half* __restrict__ K,
          const __half* __restrict__ V, __half* __restrict__ O)
{
    extern __shared__ char smem[];
    uint32_t sb = smem_u32(smem);
    int bh = blockIdx.x;
    int qt = gridDim.y - 1 - blockIdx.y;      // heavy blocks first
    int qb = qt * 64;
    int tid = threadIdx.x, lane = tid & 31, w = tid >> 5;
    int r0 = lane >> 2, qr = lane & 3;
    int l15 = lane & 15, l16 = (lane >> 4) << 4;

    const __half* qg = Q + ((size_t)bh * SEQ + qb) * HD;
    const __half* kg = K + (size_t)bh * SEQ * HD;
    const __half* vg = V + (size_t)bh * SEQ * HD;

    // stage Q tile + K/V tile 0 (rows of 64 fp16 = 128B = 8 chunks)
    #pragma unroll
    for (int i = 0; i < 4; i++) {
        int idx = tid + (i << 7);
        int row = idx >> 3, c = idx & 7;
        cp_async16(sb + ATT_QS + sw128(row * 128 + c * 16), qg + row * 64 + c * 8);
    }
    #pragma unroll
    for (int i = 0; i < 4; i++) {
        int idx = tid + (i << 7);
        int row = idx >> 3, c = idx & 7;
        cp_async16(sb + ATT_KS(0) + sw128(row * 128 + c * 16), kg + row * 64 + c * 8);
        cp_async16(sb + ATT_VS(0) + row * 144 + c * 16,        vg + row * 64 + c * 8);
    }
    CP_COMMIT();

    float o[8][4];
    #pragma unroll
    for (int nt = 0; nt < 8; nt++)
        #pragma unroll
        for (int j = 0; j < 4; j++) o[nt][j] = 0.f;
    float m0 = -INFINITY, m1 = -INFINITY, l0 = 0.f, l1 = 0.f;

    int ra = w * 16 + r0;
    int rq0 = qb + ra, rq1 = rq0 + 8;
    int ntile = qt + 1;

    for (int t = 0; t < ntile; t++) {
        int buf = t & 1;
        if (t + 1 < ntile) {
            int tn = (t + 1) * 64;
            #pragma unroll
            for (int i = 0; i < 4; i++) {
                int idx = tid + (i << 7);
                int row = idx >> 3, c = idx & 7;
                cp_async16(sb + ATT_KS(buf ^ 1) + sw128(row * 128 + c * 16),
                           kg + (size_t)(tn + row) * 64 + c * 8);
                cp_async16(sb + ATT_VS(buf ^ 1) + row * 144 + c * 16,
                           vg + (size_t)(tn + row) * 64 + c * 8);
            }
            CP_COMMIT();
            CP_WAIT(1);
        } else {
            CP_WAIT(0);
        }
        __syncthreads();

        uint32_t Qs = sb + ATT_QS;
        uint32_t Ks = sb + ATT_KS(buf);
        uint32_t Vs = sb + ATT_VS(buf);

        // ---- S = (Q * 0.125*log2e) @ K^T  -> scores already in log2 domain ----
        float s[8][4];
        #pragma unroll
        for (int nt = 0; nt < 8; nt++)
            #pragma unroll
            for (int j = 0; j < 4; j++) s[nt][j] = 0.f;

        #pragma unroll
        for (int kk = 0; kk < 64; kk += 16) {
            uint32_t a[4];
            ldsm4(a, Qs + sw128((uint32_t)((w * 16 + l15) * 128 + kk * 2 + l16)));
            #pragma unroll
            for (int p = 0; p < 4; p++) {
                uint32_t bb[4];
                ldsm4(bb, Ks + sw128((uint32_t)((p * 16 + l15) * 128 + kk * 2 + l16)));
                mma_f16(s[2 * p],     a, bb[0], bb[2]);
                mma_f16(s[2 * p + 1], a, bb[1], bb[3]);
            }
        }

        // ---- mask (diag tile), online softmax in exp2 domain ----
        int t0 = t * 64;
        bool diag = (t == qt);
        float tm0 = -INFINITY, tm1 = -INFINITY;
        #pragma unroll
        for (int nt = 0; nt < 8; nt++) {
            int c = t0 + nt * 8 + (qr << 1);
            if (diag) {
                if (c     > rq0) s[nt][0] = -INFINITY;
                if (c + 1 > rq0) s[nt][1] = -INFINITY;
                if (c     > rq1) s[nt][2] = -INFINITY;
                if (c + 1 > rq1) s[nt][3] = -INFINITY;
            }
            tm0 = fmaxf(tm0, fmaxf(s[nt][0], s[nt][1]));
            tm1 = fmaxf(tm1, fmaxf(s[nt][2], s[nt][3]));
        }
        tm0 = fmaxf(tm0, __shfl_xor_sync(0xffffffffu, tm0, 1));
        tm0 = fmaxf(tm0, __shfl_xor_sync(0xffffffffu, tm0, 2));
        tm1 = fmaxf(tm1, __shfl_xor_sync(0xffffffffu, tm1, 1));
        tm1 = fmaxf(tm1, __shfl_xor_sync(0xffffffffu, tm1, 2));

        float mn0 = fmaxf(m0, tm0), mn1 = fmaxf(m1, tm1);
        float al0 = exp2f(m0 - mn0), al1 = exp2f(m1 - mn1);
        m0 = mn0; m1 = mn1;

        float ps0 = 0.f, ps1 = 0.f;
        #pragma unroll
        for (int nt = 0; nt < 8; nt++) {
            s[nt][0] = exp2f(s[nt][0] - mn0);
            s[nt][1] = exp2f(s[nt][1] - mn0);
            s[nt][2] = exp2f(s[nt][2] - mn1);
            s[nt][3] = exp2f(s[nt][3] - mn1);
            ps0 += s[nt][0] + s[nt][1];
            ps1 += s[nt][2] + s[nt][3];
        }
        ps0 += __shfl_xor_sync(0xffffffffu, ps0, 1);
        ps0 += __shfl_xor_sync(0xffffffffu, ps0, 2);
        ps1 += __shfl_xor_sync(0xffffffffu, ps1, 1);
        ps1 += __shfl_xor_sync(0xffffffffu, ps1, 2);
        l0 = l0 * al0 + ps0;
        l1 = l1 * al1 + ps1;

        #pragma unroll
        for (int nt = 0; nt < 8; nt++) {
            o[nt][0] *= al0; o[nt][1] *= al0;
            o[nt][2] *= al1; o[nt][3] *= al1;
        }

        // ---- O += P @ V : P a-frags built directly from S c-frags (no smem) ----
        #pragma unroll
        for (int i = 0; i < 4; i++) {      // kk = 16*i
            uint32_t a[4];
            a[0] = pack_h2(s[2 * i][0],     s[2 * i][1]);
            a[1] = pack_h2(s[2 * i][2],     s[2 * i][3]);
            a[2] = pack_h2(s[2 * i + 1][0], s[2 * i + 1][1]);
            a[3] = pack_h2(s[2 * i + 1][2], s[2 * i + 1][3]);
            #pragma unroll
            for (int p = 0; p < 4; p++) {
                uint32_t bb[4];
                ldsm4t(bb, Vs + (uint32_t)((16 * i + l15) * 144 + p * 32 + l16));
                mma_f16(o[2 * p],     a, bb[0], bb[1]);
                mma_f16(o[2 * p + 1], a, bb[2], bb[3]);
            }
        }
        __syncthreads();
    }

    // ---- epilogue: O /= l, head-interleaved fp16 store into [B,S,D] ----
    float i0 = 1.0f / l0, i1 = 1.0f / l1;
    int b = bh >> 4, h = bh & 15;
    int q0 = qb + ra;
    __half* op0 = O + ((size_t)(b * SEQ + q0)) * DIM + h * 64;
    __half* op1 = op0 + 8 * DIM;
    #pragma unroll
    for (int nt = 0; nt < 8; nt++) {
        int c = nt * 8 + (qr << 1);
        *(__half2*)(op0 + c) = __floats2half2_rn(o[nt][0] * i0, o[nt][1] * i0);
        *(__half2*)(op1 + c) = __floats2half2_rn(o[nt][2] * i1, o[nt][3] * i1);
    }
}

// ---------------- launcher ----------------
extern "C" void kernel_launch(void* const* d_in, const int* in_sizes, int n_in,
                              void* d_out, int out_size)
{
    const float* x     = (const float*)d_in[0];
    const float* ln1_s = (const float*)d_in[1];
    const float* ln1_b = (const float*)d_in[2];
    const float* wq    = (const float*)d_in[3];
    const float* wk    = (const float*)d_in[4];
    const float* wv    = (const float*)d_in[5];
    const float* w_out = (const float*)d_in[6];
    const float* b_out = (const float*)d_in[7];
    const float* ln2_s = (const float*)d_in[8];
    const float* ln2_b = (const float*)d_in[9];
    const float* w1    = (const float*)d_in[10];
    const float* b1    = (const float*)d_in[11];
    const float* w2    = (const float*)d_in[12];
    const float* b2    = (const float*)d_in[13];
    float* out = (float*)d_out;

    __half *xn, *q, *k, *v, *ctx, *xn2, *h1, *wh;
    float *res1;
    cudaGetSymbolAddress((void**)&xn,   g_xn);
    cudaGetSymbolAddress((void**)&q,    g_q);
    cudaGetSymbolAddress((void**)&k,    g_k);
    cudaGetSymbolAddress((void**)&v,    g_v);
    cudaGetSymbolAddress((void**)&ctx,  g_ctx);
    cudaGetSymbolAddress((void**)&res1, g_res1);
    cudaGetSymbolAddress((void**)&xn2,  g_xn2);
    cudaGetSymbolAddress((void**)&h1,   g_h1);
    cudaGetSymbolAddress((void**)&wh,   g_wh);

    __half* wqkv_h = wh;
    __half* wo_h   = wh + 3 * 1048576;
    __half* w1_h   = wh + 4 * 1048576;
    __half* w2_h   = wh + 8 * 1048576;

    cudaFuncSetAttribute(mma_gemm<EPI_BIASRES>, cudaFuncAttributeMaxDynamicSharedMemorySize, SM_BYTES);
    cudaFuncSetAttribute(mma_gemm<EPI_GELU>,    cudaFuncAttributeMaxDynamicSharedMemorySize, SM_BYTES);
    cudaFuncSetAttribute(mma_gemm_qkv,          cudaFuncAttributeMaxDynamicSharedMemorySize, SM_BYTES);
    cudaFuncSetAttribute(fa_kernel,             cudaFuncAttributeMaxDynamicSharedMemorySize, ATT_BYTES);

    // 0) convert all weights to fp16 in one launch
    cvt_all<<<12288, 256>>>((const float4*)wq, (const float4*)wk, (const float4*)wv,
                            (const float4*)w_out, (const float4*)w1, (const float4*)w2,
                            (__half2*)wh);

    // 1) LN1 -> fp16
    ln_kernel<<<NTOK, 256>>>(x, ln1_s, ln1_b, xn);

    // 2) fused QKV projection (head-split fp16 store, q pre-scaled to log2 domain)
    dim3 gqkv(24, NTOK / 128);
    mma_gemm_qkv<<<gqkv, 256, SM_BYTES>>>(xn, wqkv_h, q, k, v);

    // 3) causal flash attention (fp16 tensor cores, register P, exp2 softmax)
    dim3 gattn(BATCH * NHEAD, SEQ / 64);
    fa_kernel<<<gattn, 128, ATT_BYTES>>>(q, k, v, ctx);

    // 4) out projection + bias + residual(x) -> fp32
    dim3 gproj(DIM / 128, NTOK / 128);
    mma_gemm<EPI_BIASRES><<<gproj, 256, SM_BYTES>>>(ctx, wo_h, b_out, x, res1, NTOK, DIM, DIM);

    // 5) LN2 -> fp16
    ln_kernel<<<NTOK, 256>>>(res1, ln2_s, ln2_b, xn2);

    // 6) MLP up + GELU -> fp16
    dim3 gup(FF / 128, NTOK / 128);
    mma_gemm<EPI_GELU><<<gup, 256, SM_BYTES>>>(xn2, w1_h, b1, nullptr, h1, NTOK, FF, DIM);

    // 7) MLP down + bias + residual(res1) -> fp32 out
    mma_gemm<EPI_BIASRES><<<gproj, 256, SM_BYTES>>>(h1, w2_h, b2, res1, out, NTOK, DIM, FF);
}

// round 16
// speedup vs baseline: 1.0491x; 1.0491x over previous
#include <cuda_runtime.h>
#include <cuda_fp16.h>
#include <math.h>
#include <stdint.h>

// Problem dims (fixed by reference)
#define DIM    1024
#define SEQ    2048
#define BATCH  2
#define NTOK   4096     // BATCH*SEQ
#define NHEAD  16
#define HD     64
#define FF     4096

// ---------------- scratch (static device globals; no allocs allowed) ----------------
__device__ __half g_xn  [NTOK * DIM];   // LN1 output (fp16)
__device__ __half g_q   [NTOK * DIM];   // [B,H,S,hd] fp16 (pre-scaled by 0.125*log2e)
__device__ __half g_k   [NTOK * DIM];
__device__ __half g_v   [NTOK * DIM];
__device__ __half g_ctx [NTOK * DIM];   // attention output fp16
__device__ float  g_res1[NTOK * DIM];   // attn_out + x (fp32)
__device__ __half g_xn2 [NTOK * DIM];   // LN2 output fp16
__device__ __half g_h1  [NTOK * FF];    // gelu(...) fp16
__device__ __half g_wh  [12 * 1024 * 1024];  // fp16 weights: wq|wk|wv|wo|w1|w2

// ---------------- PTX helpers ----------------
__device__ __forceinline__ uint32_t smem_u32(const void* p) {
    uint32_t a;
    asm("{ .reg .u64 t; cvta.to.shared.u64 t, %1; cvt.u32.u64 %0, t; }" : "=r"(a) : "l"(p));
    return a;
}
__device__ __forceinline__ void cp_async16(uint32_t dst, const void* src) {
    asm volatile("cp.async.cg.shared.global [%0], [%1], 16;" :: "r"(dst), "l"(src));
}
#define CP_COMMIT() asm volatile("cp.async.commit_group;" ::: "memory")
#define CP_WAIT(n)  asm volatile("cp.async.wait_group %0;" :: "n"(n) : "memory")

__device__ __forceinline__ void ldsm4(uint32_t* r, uint32_t addr) {
    asm volatile("ldmatrix.sync.aligned.m8n8.x4.shared.b16 {%0,%1,%2,%3}, [%4];"
        : "=r"(r[0]), "=r"(r[1]), "=r"(r[2]), "=r"(r[3]) : "r"(addr));
}
__device__ __forceinline__ void ldsm4t(uint32_t* r, uint32_t addr) {
    asm volatile("ldmatrix.sync.aligned.m8n8.x4.trans.shared.b16 {%0,%1,%2,%3}, [%4];"
        : "=r"(r[0]), "=r"(r[1]), "=r"(r[2]), "=r"(r[3]) : "r"(addr));
}
__device__ __forceinline__ void ldsm2t(uint32_t* r, uint32_t addr) {
    asm volatile("ldmatrix.sync.aligned.m8n8.x2.trans.shared.b16 {%0,%1}, [%2];"
        : "=r"(r[0]), "=r"(r[1]) : "r"(addr));
}
__device__ __forceinline__ void mma_f16(float* d, const uint32_t* a, uint32_t b0, uint32_t b1) {
    asm volatile("mma.sync.aligned.m16n8k16.row.col.f32.f16.f16.f32 "
                 "{%0,%1,%2,%3}, {%4,%5,%6,%7}, {%8,%9}, {%0,%1,%2,%3};"
                 : "+f"(d[0]), "+f"(d[1]), "+f"(d[2]), "+f"(d[3])
                 : "r"(a[0]), "r"(a[1]), "r"(a[2]), "r"(a[3]), "r"(b0), "r"(b1));
}
__device__ __forceinline__ uint32_t sw128(uint32_t off) {
    return off ^ ((off >> 3) & 0x70);
}
__device__ __forceinline__ uint32_t pack_h2(float x, float y) {
    __half2 h = __floats2half2_rn(x, y);
    return *(uint32_t*)&h;
}
__device__ __forceinline__ uint32_t h2exp2(uint32_t x) {
    uint32_t r;
    asm("ex2.approx.f16x2 %0, %1;" : "=r"(r) : "r"(x));
    return r;
}

// ---------------- fused weight-cvt + LN1 (single launch; independent halves) ----------------
__device__ __forceinline__ void ln_body(const float* __restrict__ x,
                                        const float* __restrict__ scale,
                                        const float* __restrict__ shift,
                                        __half* __restrict__ out, int row, int t)
{
    const float4* xr = (const float4*)(x + (size_t)row * DIM);
    float4 v = xr[t];
    float s  = v.x + v.y + v.z + v.w;
    float sq = v.x*v.x + v.y*v.y + v.z*v.z + v.w*v.w;
    #pragma unroll
    for (int o = 16; o > 0; o >>= 1) {
        s  += __shfl_xor_sync(0xffffffffu, s,  o);
        sq += __shfl_xor_sync(0xffffffffu, sq, o);
    }
    __shared__ float sbuf[18];
    int w = t >> 5, l = t & 31;
    if (l == 0) { sbuf[w] = s; sbuf[8 + w] = sq; }
    __syncthreads();
    if (t == 0) {
        float ts = 0.f, tq = 0.f;
        #pragma unroll
        for (int i = 0; i < 8; i++) { ts += sbuf[i]; tq += sbuf[8 + i]; }
        float mean = ts * (1.0f / 1024.0f);
        float var  = (tq - 1024.0f * mean * mean) * (1.0f / 1023.0f);
        sbuf[16] = mean;
        sbuf[17] = rsqrtf(var + 1e-5f);
    }
    __syncthreads();
    float mean = sbuf[16], inv = sbuf[17];
    float4 sc = ((const float4*)scale)[t];
    float4 sh = ((const float4*)shift)[t];
    __half2* op = (__half2*)(out + (size_t)row * DIM) + t * 2;
    op[0] = __floats2half2_rn((v.x - mean) * inv * sc.x + sh.x,
                              (v.y - mean) * inv * sc.y + sh.y);
    op[1] = __floats2half2_rn((v.z - mean) * inv * sc.z + sh.z,
                              (v.w - mean) * inv * sc.w + sh.w);
}

__global__ void cvt_ln(const float4* __restrict__ wq, const float4* __restrict__ wk,
                       const float4* __restrict__ wv, const float4* __restrict__ wo,
                       const float4* __restrict__ w1, const float4* __restrict__ w2,
                       __half2* __restrict__ dst,
                       const float* __restrict__ x, const float* __restrict__ ln_s,
                       const float* __restrict__ ln_b, __half* __restrict__ xn)
{
    if (blockIdx.x < 12288) {
        int i = blockIdx.x * 256 + threadIdx.x;   // float4 index
        const float4* s;
        int j;
        if (i < 1048576) {
            int seg = i >> 18;
            j = i & 262143;
            s = (seg == 0) ? wq : (seg == 1) ? wk : (seg == 2) ? wv : wo;
        } else if (i < 2097152) {
            s = w1; j = i - 1048576;
        } else {
            s = w2; j = i - 2097152;
        }
        float4 v = s[j];
        dst[i * 2]     = __floats2half2_rn(v.x, v.y);
        dst[i * 2 + 1] = __floats2half2_rn(v.z, v.w);
    } else {
        ln_body(x, ln_s, ln_b, xn, blockIdx.x - 12288, threadIdx.x);
    }
}

// standalone LN (for LN2)
__global__ void ln_kernel(const float* __restrict__ x,
                          const float* __restrict__ scale,
                          const float* __restrict__ shift,
                          __half* __restrict__ out)
{
    ln_body(x, scale, shift, out, blockIdx.x, threadIdx.x);
}

// ---------------- fp16 mma GEMM, 128x128 CTA tile, 8 warps, K-chunk 64, 2-stage ----------------
#define EPI_QKV     0
#define EPI_BIASRES 1
#define EPI_GELU    2

__device__ __forceinline__ float gelu_tanh(float x) {
    float t = 0.7978845608028654f * (x + 0.044715f * x * x * x);
    return 0.5f * x * (1.0f + tanhf(t));
}

// smem: A[2] 128 rows x 128B SW128 = 16KB each; B[2] 64 k-rows x 272B pitch
#define SM_A(buf)  ((buf) * 16384)
#define SM_B(buf)  (32768 + (buf) * 17408)
#define SM_BYTES   (32768 + 2 * 17408)

template<int EPI>
__device__ __forceinline__ void epi_store(void* __restrict__ Cv,
                                          const float* __restrict__ bias,
                                          const float* __restrict__ resid,
                                          int N, int r, int c, float v0, float v1,
                                          float oscale)
{
    if (EPI == EPI_QKV) {
        __half* C = (__half*)Cv;
        int b = r >> 11, s = r & 2047;
        int h = c >> 6, d = c & 63;
        __half* dst = C + (((size_t)(b * NHEAD + h) * SEQ) + s) * HD + d;
        *(__half2*)dst = __floats2half2_rn(v0 * oscale, v1 * oscale);
    } else if (EPI == EPI_BIASRES) {
        float* C = (float*)Cv;
        size_t idx = (size_t)r * N + c;
        *(float2*)(C + idx) = make_float2(v0 + bias[c]     + resid[idx],
                                          v1 + bias[c + 1] + resid[idx + 1]);
    } else { // EPI_GELU -> fp16
        __half* C = (__half*)Cv;
        size_t idx = (size_t)r * N + c;
        *(__half2*)(C + idx) = __floats2half2_rn(gelu_tanh(v0 + bias[c]),
                                                 gelu_tanh(v1 + bias[c + 1]));
    }
}

__device__ __forceinline__ void stage_tiles(uint32_t sb, int buf,
    const __half* __restrict__ A, const __half* __restrict__ W,
    int bm, int bn, int ch, int K, int N, int tid)
{
    #pragma unroll
    for (int i = 0; i < 4; i++) {
        int idx = tid + (i << 8);
        int row = idx >> 3, c = idx & 7;
        const void* src = A + (size_t)(bm + row) * K + ch * 64 + c * 8;
        cp_async16(sb + SM_A(buf) + sw128(row * 128 + c * 16), src);
    }
    #pragma unroll
    for (int i = 0; i < 4; i++) {
        int idx = tid + (i << 8);
        int row = idx >> 4, c = idx & 15;
        const void* src = W + (size_t)(ch * 64 + row) * N + bn + c * 8;
        cp_async16(sb + SM_B(buf) + row * 272 + c * 16, src);
    }
}

template<int EPI>
__device__ __forceinline__ void gemm_body(
    const __half* __restrict__ A, const __half* __restrict__ W,
    const float* __restrict__ bias, const float* __restrict__ resid,
    void* __restrict__ C, int N, int K, int bm, int bn,
    uint32_t sb, int tid, float oscale)
{
    int lane = tid & 31, wid = tid >> 5;
    int wm = (wid >> 2) * 64, wn = (wid & 3) * 32;

    float acc[4][4][4];
    #pragma unroll
    for (int i = 0; i < 4; i++)
        #pragma unroll
        for (int j = 0; j < 4; j++)
            #pragma unroll
            for (int q = 0; q < 4; q++) acc[i][j][q] = 0.f;

    int nch = K >> 6;

    stage_tiles(sb, 0, A, W, bm, bn, 0, K, N, tid);
    CP_COMMIT();

    int buf = 0;
    int l15 = lane & 15, l16 = (lane >> 4) << 4;
    for (int ch = 0; ch < nch; ch++) {
        CP_WAIT(0);
        __syncthreads();
        if (ch + 1 < nch) {
            stage_tiles(sb, buf ^ 1, A, W, bm, bn, ch + 1, K, N, tid);
            CP_COMMIT();
        }

        uint32_t As = sb + SM_A(buf);
        uint32_t Bs = sb + SM_B(buf);
        #pragma unroll
        for (int kk = 0; kk < 64; kk += 16) {
            uint32_t a[4][4];
            #pragma unroll
            for (int mt = 0; mt < 4; mt++) {
                int row = wm + mt * 16 + l15;
                ldsm4(a[mt], As + sw128((uint32_t)(row * 128 + kk * 2 + l16)));
            }
            #pragma unroll
            for (int p = 0; p < 2; p++) {
                uint32_t bb[4];
                ldsm4t(bb, Bs + (uint32_t)((kk + l15) * 272 + (wn + p * 16) * 2 + l16));
                #pragma unroll
                for (int mt = 0; mt < 4; mt++) {
                    mma_f16(acc[mt][2 * p],     a[mt], bb[0], bb[1]);
                    mma_f16(acc[mt][2 * p + 1], a[mt], bb[2], bb[3]);
                }
            }
        }
        buf ^= 1;
    }

    #pragma unroll
    for (int mt = 0; mt < 4; mt++) {
        int r0 = bm + wm + mt * 16 + (lane >> 2);
        #pragma unroll
        for (int nt = 0; nt < 4; nt++) {
            int c0 = bn + wn + nt * 8 + ((lane & 3) << 1);
            epi_store<EPI>(C, bias, resid, N, r0,     c0, acc[mt][nt][0], acc[mt][nt][1], oscale);
            epi_store<EPI>(C, bias, resid, N, r0 + 8, c0, acc[mt][nt][2], acc[mt][nt][3], oscale);
        }
    }
}

template<int EPI>
__global__ void __launch_bounds__(256, 2)
mma_gemm(const __half* __restrict__ A, const __half* __restrict__ W,
         const float* __restrict__ bias, const float* __restrict__ resid,
         void* __restrict__ C, int M, int N, int K)
{
    extern __shared__ char smem[];
    uint32_t sb = smem_u32(smem);
    int bm = blockIdx.y * 128, bn = blockIdx.x * 128;
    gemm_body<EPI>(A, W, bias, resid, C, N, K, bm, bn, sb, threadIdx.x, 1.0f);
}

// fused QKV: grid.x = 24 (8 n-tiles x 3 weights); q pre-scaled by 0.125*log2(e)
#define QSCALE 0.18033688011112042f   // (1/8) * log2(e)

__global__ void __launch_bounds__(256, 2)
mma_gemm_qkv(const __half* __restrict__ A, const __half* __restrict__ wqkv,
             __half* __restrict__ q, __half* __restrict__ k, __half* __restrict__ v)
{
    extern __shared__ char smem[];
    uint32_t sb = smem_u32(smem);
    int seg = blockIdx.x >> 3;
    int bn  = (blockIdx.x & 7) * 128;
    int bm  = blockIdx.y * 128;
    const __half* W = wqkv + (size_t)seg * (DIM * DIM);
    __half* C = (seg == 0) ? q : (seg == 1) ? k : v;
    float sc = (seg == 0) ? QSCALE : 1.0f;
    gemm_body<EPI_QKV>(A, W, nullptr, nullptr, C, DIM, DIM, bm, bn, sb, threadIdx.x, sc);
}

// ---------------- fp16 mma flash attention (register P, f16x2 exp2, mma row-sum) ----------------
// 1 CTA = 64 q rows of one (b,h); 4 warps; Bc=64, double-buffered K/V.
// Q/K: 64 rows x 128B SW128 (8KB each). V: 64 rows x 144B pitch (9216B each);
// bytes 128..143 of each V row = ones-column pad [1,0,0,0,0,0,0,0] for mma row-sums.
#define ATT_QS      0
#define ATT_KS(b)   (8192 + (b) * 8192)
#define ATT_VS(b)   (24576 + (b) * 9216)
#define ATT_BYTES   43008

__global__ void __launch_bounds__(128, 4)
fa_kernel(const __half* __restrict__ Q, const __half* __restrict__ K,
          const __half* __restrict__ V, __half* __restrict__ O)
{
    extern __shared__ char smem[];
    uint32_t sb = smem_u32(smem);
    int bh = blockIdx.x;
    int qt = gridDim.y - 1 - blockIdx.y;      // heavy blocks first
    int qb = qt * 64;
    int tid = threadIdx.x, lane = tid & 31, w = tid >> 5;
    int r0 = lane >> 2, qr = lane & 3;
    int l15 = lane & 15, l16 = (lane >> 4) << 4;

    const __half* qg = Q + ((size_t)bh * SEQ + qb) * HD;
    const __half* kg = K + (size_t)bh * SEQ * HD;
    const __half* vg = V + (size_t)bh * SEQ * HD;

    // init V pad (ones column) for both buffers: 128 threads x one 16B chunk
    {
        int vbuf = tid >> 6, row = tid & 63;
        uint4* pad = (uint4*)(smem + ATT_VS(vbuf) + row * 144 + 128);
        *pad = make_uint4(0x00003C00u, 0u, 0u, 0u);   // {1.0h, 0, 0, ...}
    }

    // stage Q tile + K/V tile 0 (rows of 64 fp16 = 128B = 8 chunks)
    #pragma unroll
    for (int i = 0; i < 4; i++) {
        int idx = tid + (i << 7);
        int row = idx >> 3, c = idx & 7;
        cp_async16(sb + ATT_QS + sw128(row * 128 + c * 16), qg + row * 64 + c * 8);
    }
    #pragma unroll
    for (int i = 0; i < 4; i++) {
        int idx = tid + (i << 7);
        int row = idx >> 3, c = idx & 7;
        cp_async16(sb + ATT_KS(0) + sw128(row * 128 + c * 16), kg + row * 64 + c * 8);
        cp_async16(sb + ATT_VS(0) + row * 144 + c * 16,        vg + row * 64 + c * 8);
    }
    CP_COMMIT();

    float o[8][4];
    #pragma unroll
    for (int nt = 0; nt < 8; nt++)
        #pragma unroll
        for (int j = 0; j < 4; j++) o[nt][j] = 0.f;
    float ol[4] = {0.f, 0.f, 0.f, 0.f};    // ones-column accumulator (row sums)
    float m0 = -INFINITY, m1 = -INFINITY;

    int ra = w * 16 + r0;
    int rq0 = qb + ra, rq1 = rq0 + 8;
    int ntile = qt + 1;

    for (int t = 0; t < ntile; t++) {
        int buf = t & 1;
        if (t + 1 < ntile) {
            int tn = (t + 1) * 64;
            #pragma unroll
            for (int i = 0; i < 4; i++) {
                int idx = tid + (i << 7);
                int row = idx >> 3, c = idx & 7;
                cp_async16(sb + ATT_KS(buf ^ 1) + sw128(row * 128 + c * 16),
                           kg + (size_t)(tn + row) * 64 + c * 8);
                cp_async16(sb + ATT_VS(buf ^ 1) + row * 144 + c * 16,
                           vg + (size_t)(tn + row) * 64 + c * 8);
            }
            CP_COMMIT();
            CP_WAIT(1);
        } else {
            CP_WAIT(0);
        }
        __syncthreads();

        uint32_t Qs = sb + ATT_QS;
        uint32_t Ks = sb + ATT_KS(buf);
        uint32_t Vs = sb + ATT_VS(buf);

        // ---- S = (Q * 0.125*log2e) @ K^T  -> scores in log2 domain ----
        float s[8][4];
        #pragma unroll
        for (int nt = 0; nt < 8; nt++)
            #pragma unroll
            for (int j = 0; j < 4; j++) s[nt][j] = 0.f;

        #pragma unroll
        for (int kk = 0; kk < 64; kk += 16) {
            uint32_t a[4];
            ldsm4(a, Qs + sw128((uint32_t)((w * 16 + l15) * 128 + kk * 2 + l16)));
            #pragma unroll
            for (int p = 0; p < 4; p++) {
                uint32_t bb[4];
                ldsm4(bb, Ks + sw128((uint32_t)((p * 16 + l15) * 128 + kk * 2 + l16)));
                mma_f16(s[2 * p],     a, bb[0], bb[2]);
                mma_f16(s[2 * p + 1], a, bb[1], bb[3]);
            }
        }

        // ---- mask (diag tile), running max ----
        int t0 = t * 64;
        bool diag = (t == qt);
        float tm0 = -INFINITY, tm1 = -INFINITY;
        #pragma unroll
        for (int nt = 0; nt < 8; nt++) {
            int c = t0 + nt * 8 + (qr << 1);
            if (diag) {
                if (c     > rq0) s[nt][0] = -INFINITY;
                if (c + 1 > rq0) s[nt][1] = -INFINITY;
                if (c     > rq1) s[nt][2] = -INFINITY;
                if (c + 1 > rq1) s[nt][3] = -INFINITY;
            }
            tm0 = fmaxf(tm0, fmaxf(s[nt][0], s[nt][1]));
            tm1 = fmaxf(tm1, fmaxf(s[nt][2], s[nt][3]));
        }
        tm0 = fmaxf(tm0, __shfl_xor_sync(0xffffffffu, tm0, 1));
        tm0 = fmaxf(tm0, __shfl_xor_sync(0xffffffffu, tm0, 2));
        tm1 = fmaxf(tm1, __shfl_xor_sync(0xffffffffu, tm1, 1));
        tm1 = fmaxf(tm1, __shfl_xor_sync(0xffffffffu, tm1, 2));

        float mn0 = fmaxf(m0, tm0), mn1 = fmaxf(m1, tm1);
        float al0 = exp2f(m0 - mn0), al1 = exp2f(m1 - mn1);
        m0 = mn0; m1 = mn1;

        // ---- P = exp2(S - m) packed to half2 a-frags (one MUFU per pair) ----
        uint32_t pf[16];
        #pragma unroll
        for (int nt = 0; nt < 8; nt++) {
            pf[2 * nt]     = h2exp2(pack_h2(s[nt][0] - mn0, s[nt][1] - mn0));
            pf[2 * nt + 1] = h2exp2(pack_h2(s[nt][2] - mn1, s[nt][3] - mn1));
        }

        // rescale accumulators
        #pragma unroll
        for (int nt = 0; nt < 8; nt++) {
            o[nt][0] *= al0; o[nt][1] *= al0;
            o[nt][2] *= al1; o[nt][3] *= al1;
        }
        ol[0] *= al0; ol[1] *= al0; ol[2] *= al1; ol[3] *= al1;

        // ---- O += P @ [V | 1] : ones column accumulates row sums ----
        #pragma unroll
        for (int i = 0; i < 4; i++) {      // kk = 16*i
            const uint32_t* a = &pf[4 * i];
            #pragma unroll
            for (int p = 0; p < 4; p++) {
                uint32_t bb[4];
                ldsm4t(bb, Vs + (uint32_t)((16 * i + l15) * 144 + p * 32 + l16));
                mma_f16(o[2 * p],     a, bb[0], bb[1]);
                mma_f16(o[2 * p + 1], a, bb[2], bb[3]);
            }
            uint32_t bl[2];
            ldsm2t(bl, Vs + (uint32_t)((16 * i + l15) * 144 + 128));
            mma_f16(ol, a, bl[0], bl[1]);
        }
        __syncthreads();
    }

    // ---- epilogue: l from ones-column (qr==0 lane, col 64), broadcast in quad ----
    float l0 = __shfl_sync(0xffffffffu, ol[0], lane & ~3);
    float l1 = __shfl_sync(0xffffffffu, ol[2], lane & ~3);
    float i0 = 1.0f / l0, i1 = 1.0f / l1;
    int b = bh >> 4, h = bh & 15;
    int q0 = qb + ra;
    __half* op0 = O + ((size_t)(b * SEQ + q0)) * DIM + h * 64;
    __half* op1 = op0 + 8 * DIM;
    #pragma unroll
    for (int nt = 0; nt < 8; nt++) {
        int c = nt * 8 + (qr << 1);
        *(__half2*)(op0 + c) = __floats2half2_rn(o[nt][0] * i0, o[nt][1] * i0);
        *(__half2*)(op1 + c) = __floats2half2_rn(o[nt][2] * i1, o[nt][3] * i1);
    }
}

// ---------------- launcher ----------------
extern "C" void kernel_launch(void* const* d_in, const int* in_sizes, int n_in,
                              void* d_out, int out_size)
{
    const float* x     = (const float*)d_in[0];
    const float* ln1_s = (const float*)d_in[1];
    const float* ln1_b = (const float*)d_in[2];
    const float* wq    = (const float*)d_in[3];
    const float* wk    = (const float*)d_in[4];
    const float* wv    = (const float*)d_in[5];
    const float* w_out = (const float*)d_in[6];
    const float* b_out = (const float*)d_in[7];
    const float* ln2_s = (const float*)d_in[8];
    const float* ln2_b = (const float*)d_in[9];
    const float* w1    = (const float*)d_in[10];
    const float* b1    = (const float*)d_in[11];
    const float* w2    = (const float*)d_in[12];
    const float* b2    = (const float*)d_in[13];
    float* out = (float*)d_out;

    __half *xn, *q, *k, *v, *ctx, *xn2, *h1, *wh;
    float *res1;
    cudaGetSymbolAddress((void**)&xn,   g_xn);
    cudaGetSymbolAddress((void**)&q,    g_q);
    cudaGetSymbolAddress((void**)&k,    g_k);
    cudaGetSymbolAddress((void**)&v,    g_v);
    cudaGetSymbolAddress((void**)&ctx,  g_ctx);
    cudaGetSymbolAddress((void**)&res1, g_res1);
    cudaGetSymbolAddress((void**)&xn2,  g_xn2);
    cudaGetSymbolAddress((void**)&h1,   g_h1);
    cudaGetSymbolAddress((void**)&wh,   g_wh);

    __half* wqkv_h = wh;
    __half* wo_h   = wh + 3 * 1048576;
    __half* w1_h   = wh + 4 * 1048576;
    __half* w2_h   = wh + 8 * 1048576;

    cudaFuncSetAttribute(mma_gemm<EPI_BIASRES>, cudaFuncAttributeMaxDynamicSharedMemorySize, SM_BYTES);
    cudaFuncSetAttribute(mma_gemm<EPI_GELU>,    cudaFuncAttributeMaxDynamicSharedMemorySize, SM_BYTES);
    cudaFuncSetAttribute(mma_gemm_qkv,          cudaFuncAttributeMaxDynamicSharedMemorySize, SM_BYTES);
    cudaFuncSetAttribute(fa_kernel,             cudaFuncAttributeMaxDynamicSharedMemorySize, ATT_BYTES);

    // 0+1) weight cvt + LN1 fused into one launch
    cvt_ln<<<12288 + NTOK, 256>>>((const float4*)wq, (const float4*)wk, (const float4*)wv,
                                  (const float4*)w_out, (const float4*)w1, (const float4*)w2,
                                  (__half2*)wh, x, ln1_s, ln1_b, xn);

    // 2) fused QKV projection (head-split fp16 store, q pre-scaled to log2 domain)
    dim3 gqkv(24, NTOK / 128);
    mma_gemm_qkv<<<gqkv, 256, SM_BYTES>>>(xn, wqkv_h, q, k, v);

    // 3) causal flash attention
    dim3 gattn(BATCH * NHEAD, SEQ / 64);
    fa_kernel<<<gattn, 128, ATT_BYTES>>>(q, k, v, ctx);

    // 4) out projection + bias + residual(x) -> fp32
    dim3 gproj(DIM / 128, NTOK / 128);
    mma_gemm<EPI_BIASRES><<<gproj, 256, SM_BYTES>>>(ctx, wo_h, b_out, x, res1, NTOK, DIM, DIM);

    // 5) LN2 -> fp16
    ln_kernel<<<NTOK, 256>>>(res1, ln2_s, ln2_b, xn2);

    // 6) MLP up + GELU -> fp16
    dim3 gup(FF / 128, NTOK / 128);
    mma_gemm<EPI_GELU><<<gup, 256, SM_BYTES>>>(xn2, w1_h, b1, nullptr, h1, NTOK, FF, DIM);

    // 7) MLP down + bias + residual(res1) -> fp32 out
    mma_gemm<EPI_BIASRES><<<gproj, 256, SM_BYTES>>>(h1, w2_h, b2, res1, out, NTOK, DIM, FF);
}

// round 17
// speedup vs baseline: 1.0654x; 1.0155x over previous
#include <cuda_runtime.h>
#include <cuda_fp16.h>
#include <math.h>
#include <stdint.h>

// Problem dims (fixed by reference)
#define DIM    1024
#define SEQ    2048
#define BATCH  2
#define NTOK   4096     // BATCH*SEQ
#define NHEAD  16
#define HD     64
#define FF     4096

// ---------------- scratch (static device globals; no allocs allowed) ----------------
__device__ __half g_xn  [NTOK * DIM];   // LN1 output (fp16)
__device__ __half g_q   [NTOK * DIM];   // [B,H,S,hd] fp16 (pre-scaled by 0.125*log2e)
__device__ __half g_k   [NTOK * DIM];
__device__ __half g_v   [NTOK * DIM];
__device__ __half g_ctx [NTOK * DIM];   // attention output fp16
__device__ float  g_res1[NTOK * DIM];   // attn_out + x (fp32)
__device__ __half g_xn2 [NTOK * DIM];   // LN2 output fp16
__device__ __half g_h1  [NTOK * FF];    // gelu(...) fp16
__device__ __half g_wh  [12 * 1024 * 1024];  // fp16 weights: wq|wk|wv|wo|w1|w2

// ---------------- PTX helpers ----------------
__device__ __forceinline__ uint32_t smem_u32(const void* p) {
    uint32_t a;
    asm("{ .reg .u64 t; cvta.to.shared.u64 t, %1; cvt.u32.u64 %0, t; }" : "=r"(a) : "l"(p));
    return a;
}
__device__ __forceinline__ void cp_async16(uint32_t dst, const void* src) {
    asm volatile("cp.async.cg.shared.global [%0], [%1], 16;" :: "r"(dst), "l"(src));
}
#define CP_COMMIT() asm volatile("cp.async.commit_group;" ::: "memory")
#define CP_WAIT(n)  asm volatile("cp.async.wait_group %0;" :: "n"(n) : "memory")

__device__ __forceinline__ void ldsm4(uint32_t* r, uint32_t addr) {
    asm volatile("ldmatrix.sync.aligned.m8n8.x4.shared.b16 {%0,%1,%2,%3}, [%4];"
        : "=r"(r[0]), "=r"(r[1]), "=r"(r[2]), "=r"(r[3]) : "r"(addr));
}
__device__ __forceinline__ void ldsm4t(uint32_t* r, uint32_t addr) {
    asm volatile("ldmatrix.sync.aligned.m8n8.x4.trans.shared.b16 {%0,%1,%2,%3}, [%4];"
        : "=r"(r[0]), "=r"(r[1]), "=r"(r[2]), "=r"(r[3]) : "r"(addr));
}
__device__ __forceinline__ void ldsm2t(uint32_t* r, uint32_t addr) {
    asm volatile("ldmatrix.sync.aligned.m8n8.x2.trans.shared.b16 {%0,%1}, [%2];"
        : "=r"(r[0]), "=r"(r[1]) : "r"(addr));
}
__device__ __forceinline__ void mma_f16(float* d, const uint32_t* a, uint32_t b0, uint32_t b1) {
    asm volatile("mma.sync.aligned.m16n8k16.row.col.f32.f16.f16.f32 "
                 "{%0,%1,%2,%3}, {%4,%5,%6,%7}, {%8,%9}, {%0,%1,%2,%3};"
                 : "+f"(d[0]), "+f"(d[1]), "+f"(d[2]), "+f"(d[3])
                 : "r"(a[0]), "r"(a[1]), "r"(a[2]), "r"(a[3]), "r"(b0), "r"(b1));
}
__device__ __forceinline__ uint32_t sw128(uint32_t off) {
    return off ^ ((off >> 3) & 0x70);
}
__device__ __forceinline__ uint32_t pack_h2(float x, float y) {
    __half2 h = __floats2half2_rn(x, y);
    return *(uint32_t*)&h;
}
__device__ __forceinline__ uint32_t h2exp2(uint32_t x) {
    uint32_t r;
    asm("ex2.approx.f16x2 %0, %1;" : "=r"(r) : "r"(x));
    return r;
}
__device__ __forceinline__ void cvt_store(__half2* __restrict__ dst, int i, float4 v) {
    dst[i * 2]     = __floats2half2_rn(v.x, v.y);
    dst[i * 2 + 1] = __floats2half2_rn(v.z, v.w);
}

// ---------------- LN body ----------------
__device__ __forceinline__ void ln_body(const float* __restrict__ x,
                                        const float* __restrict__ scale,
                                        const float* __restrict__ shift,
                                        __half* __restrict__ out, int row, int t)
{
    const float4* xr = (const float4*)(x + (size_t)row * DIM);
    float4 v = xr[t];
    float s  = v.x + v.y + v.z + v.w;
    float sq = v.x*v.x + v.y*v.y + v.z*v.z + v.w*v.w;
    #pragma unroll
    for (int o = 16; o > 0; o >>= 1) {
        s  += __shfl_xor_sync(0xffffffffu, s,  o);
        sq += __shfl_xor_sync(0xffffffffu, sq, o);
    }
    __shared__ float sbuf[18];
    int w = t >> 5, l = t & 31;
    if (l == 0) { sbuf[w] = s; sbuf[8 + w] = sq; }
    __syncthreads();
    if (t == 0) {
        float ts = 0.f, tq = 0.f;
        #pragma unroll
        for (int i = 0; i < 8; i++) { ts += sbuf[i]; tq += sbuf[8 + i]; }
        float mean = ts * (1.0f / 1024.0f);
        float var  = (tq - 1024.0f * mean * mean) * (1.0f / 1023.0f);
        sbuf[16] = mean;
        sbuf[17] = rsqrtf(var + 1e-5f);
    }
    __syncthreads();
    float mean = sbuf[16], inv = sbuf[17];
    float4 sc = ((const float4*)scale)[t];
    float4 sh = ((const float4*)shift)[t];
    __half2* op = (__half2*)(out + (size_t)row * DIM) + t * 2;
    op[0] = __floats2half2_rn((v.x - mean) * inv * sc.x + sh.x,
                              (v.y - mean) * inv * sc.y + sh.y);
    op[1] = __floats2half2_rn((v.z - mean) * inv * sc.z + sh.z,
                              (v.w - mean) * inv * sc.w + sh.w);
}

// ---------------- phase-1: cvt wq/wk/wv (ILP4) + LN1 ----------------
// conv blocks: 768 (each 256 thr x 4 float4); LN blocks: NTOK
#define CVT1_BLOCKS 768
__global__ void cvt_qkv_ln(const float4* __restrict__ wq, const float4* __restrict__ wk,
                           const float4* __restrict__ wv, __half2* __restrict__ dst,
                           const float* __restrict__ x, const float* __restrict__ ln_s,
                           const float* __restrict__ ln_b, __half* __restrict__ xn)
{
    if (blockIdx.x < CVT1_BLOCKS) {
        int base = blockIdx.x * 1024 + threadIdx.x;
        float4 v[4];
        int idx[4];
        #pragma unroll
        for (int j = 0; j < 4; j++) {
            int i = base + j * 256;           // 0 .. 786431
            idx[j] = i;
            int seg = i >> 18, jj = i & 262143;
            const float4* s = (seg == 0) ? wq : (seg == 1) ? wk : wv;
            v[j] = s[jj];
        }
        #pragma unroll
        for (int j = 0; j < 4; j++) cvt_store(dst, idx[j], v[j]);
    } else {
        ln_body(x, ln_s, ln_b, xn, blockIdx.x - CVT1_BLOCKS, threadIdx.x);
    }
}

// standalone LN (for LN2)
__global__ void ln_kernel(const float* __restrict__ x,
                          const float* __restrict__ scale,
                          const float* __restrict__ shift,
                          __half* __restrict__ out)
{
    ln_body(x, scale, shift, out, blockIdx.x, threadIdx.x);
}

// ---------------- fp16 mma GEMM, 128x128 CTA tile, 8 warps, K-chunk 64, 2-stage ----------------
#define EPI_QKV     0
#define EPI_BIASRES 1
#define EPI_GELU    2

__device__ __forceinline__ float gelu_tanh(float x) {
    float t = 0.7978845608028654f * (x + 0.044715f * x * x * x);
    return 0.5f * x * (1.0f + tanhf(t));
}

// smem: A[2] 128 rows x 128B SW128 = 16KB each; B[2] 64 k-rows x 272B pitch
#define SM_A(buf)  ((buf) * 16384)
#define SM_B(buf)  (32768 + (buf) * 17408)
#define SM_BYTES   (32768 + 2 * 17408)

template<int EPI>
__device__ __forceinline__ void epi_store(void* __restrict__ Cv,
                                          const float* __restrict__ bias,
                                          const float* __restrict__ resid,
                                          int N, int r, int c, float v0, float v1,
                                          float oscale)
{
    if (EPI == EPI_QKV) {
        __half* C = (__half*)Cv;
        int b = r >> 11, s = r & 2047;
        int h = c >> 6, d = c & 63;
        __half* dst = C + (((size_t)(b * NHEAD + h) * SEQ) + s) * HD + d;
        *(__half2*)dst = __floats2half2_rn(v0 * oscale, v1 * oscale);
    } else if (EPI == EPI_BIASRES) {
        float* C = (float*)Cv;
        size_t idx = (size_t)r * N + c;
        *(float2*)(C + idx) = make_float2(v0 + bias[c]     + resid[idx],
                                          v1 + bias[c + 1] + resid[idx + 1]);
    } else { // EPI_GELU -> fp16
        __half* C = (__half*)Cv;
        size_t idx = (size_t)r * N + c;
        *(__half2*)(C + idx) = __floats2half2_rn(gelu_tanh(v0 + bias[c]),
                                                 gelu_tanh(v1 + bias[c + 1]));
    }
}

__device__ __forceinline__ void stage_tiles(uint32_t sb, int buf,
    const __half* __restrict__ A, const __half* __restrict__ W,
    int bm, int bn, int ch, int K, int N, int tid)
{
    #pragma unroll
    for (int i = 0; i < 4; i++) {
        int idx = tid + (i << 8);
        int row = idx >> 3, c = idx & 7;
        const void* src = A + (size_t)(bm + row) * K + ch * 64 + c * 8;
        cp_async16(sb + SM_A(buf) + sw128(row * 128 + c * 16), src);
    }
    #pragma unroll
    for (int i = 0; i < 4; i++) {
        int idx = tid + (i << 8);
        int row = idx >> 4, c = idx & 15;
        const void* src = W + (size_t)(ch * 64 + row) * N + bn + c * 8;
        cp_async16(sb + SM_B(buf) + row * 272 + c * 16, src);
    }
}

template<int EPI>
__device__ __forceinline__ void gemm_body(
    const __half* __restrict__ A, const __half* __restrict__ W,
    const float* __restrict__ bias, const float* __restrict__ resid,
    void* __restrict__ C, int N, int K, int bm, int bn,
    uint32_t sb, int tid, float oscale)
{
    int lane = tid & 31, wid = tid >> 5;
    int wm = (wid >> 2) * 64, wn = (wid & 3) * 32;

    float acc[4][4][4];
    #pragma unroll
    for (int i = 0; i < 4; i++)
        #pragma unroll
        for (int j = 0; j < 4; j++)
            #pragma unroll
            for (int q = 0; q < 4; q++) acc[i][j][q] = 0.f;

    int nch = K >> 6;

    stage_tiles(sb, 0, A, W, bm, bn, 0, K, N, tid);
    CP_COMMIT();

    int buf = 0;
    int l15 = lane & 15, l16 = (lane >> 4) << 4;
    for (int ch = 0; ch < nch; ch++) {
        CP_WAIT(0);
        __syncthreads();
        if (ch + 1 < nch) {
            stage_tiles(sb, buf ^ 1, A, W, bm, bn, ch + 1, K, N, tid);
            CP_COMMIT();
        }

        uint32_t As = sb + SM_A(buf);
        uint32_t Bs = sb + SM_B(buf);
        #pragma unroll
        for (int kk = 0; kk < 64; kk += 16) {
            uint32_t a[4][4];
            #pragma unroll
            for (int mt = 0; mt < 4; mt++) {
                int row = wm + mt * 16 + l15;
                ldsm4(a[mt], As + sw128((uint32_t)(row * 128 + kk * 2 + l16)));
            }
            #pragma unroll
            for (int p = 0; p < 2; p++) {
                uint32_t bb[4];
                ldsm4t(bb, Bs + (uint32_t)((kk + l15) * 272 + (wn + p * 16) * 2 + l16));
                #pragma unroll
                for (int mt = 0; mt < 4; mt++) {
                    mma_f16(acc[mt][2 * p],     a[mt], bb[0], bb[1]);
                    mma_f16(acc[mt][2 * p + 1], a[mt], bb[2], bb[3]);
                }
            }
        }
        buf ^= 1;
    }

    #pragma unroll
    for (int mt = 0; mt < 4; mt++) {
        int r0 = bm + wm + mt * 16 + (lane >> 2);
        #pragma unroll
        for (int nt = 0; nt < 4; nt++) {
            int c0 = bn + wn + nt * 8 + ((lane & 3) << 1);
            epi_store<EPI>(C, bias, resid, N, r0,     c0, acc[mt][nt][0], acc[mt][nt][1], oscale);
            epi_store<EPI>(C, bias, resid, N, r0 + 8, c0, acc[mt][nt][2], acc[mt][nt][3], oscale);
        }
    }
}

template<int EPI>
__global__ void __launch_bounds__(256, 2)
mma_gemm(const __half* __restrict__ A, const __half* __restrict__ W,
         const float* __restrict__ bias, const float* __restrict__ resid,
         void* __restrict__ C, int M, int N, int K)
{
    extern __shared__ char smem[];
    uint32_t sb = smem_u32(smem);
    int bm = blockIdx.y * 128, bn = blockIdx.x * 128;
    gemm_body<EPI>(A, W, bias, resid, C, N, K, bm, bn, sb, threadIdx.x, 1.0f);
}

// fused QKV: grid.x = 24 (8 n-tiles x 3 weights); q pre-scaled by 0.125*log2(e)
#define QSCALE 0.18033688011112042f   // (1/8) * log2(e)

__global__ void __launch_bounds__(256, 2)
mma_gemm_qkv(const __half* __restrict__ A, const __half* __restrict__ wqkv,
             __half* __restrict__ q, __half* __restrict__ k, __half* __restrict__ v)
{
    extern __shared__ char smem[];
    uint32_t sb = smem_u32(smem);
    int seg = blockIdx.x >> 3;
    int bn  = (blockIdx.x & 7) * 128;
    int bm  = blockIdx.y * 128;
    const __half* W = wqkv + (size_t)seg * (DIM * DIM);
    __half* C = (seg == 0) ? q : (seg == 1) ? k : v;
    float sc = (seg == 0) ? QSCALE : 1.0f;
    gemm_body<EPI_QKV>(A, W, nullptr, nullptr, C, DIM, DIM, bm, bn, sb, threadIdx.x, sc);
}

// ---------------- fp16 mma flash attention + hidden wo/w1/w2 conversion ----------------
// blockIdx.x <  32 : attention CTA (128 thr, 4 warps, Bc=64, double-buffered K/V)
// blockIdx.x >= 32 : conversion CTA — converts 4 float4 per thread of wo|w1|w2
// Q/K: 64 rows x 128B SW128 (8KB each). V: 64 rows x 144B pitch; ones-pad col for row sums.
#define ATT_QS      0
#define ATT_KS(b)   (8192 + (b) * 8192)
#define ATT_VS(b)   (24576 + (b) * 9216)
#define ATT_BYTES   43008
#define CVT2_XBLK   144               // grid.x = 32 + 144; conv blocks = 144*32 = 4608

__global__ void __launch_bounds__(128, 4)
fa_kernel(const __half* __restrict__ Q, const __half* __restrict__ K,
          const __half* __restrict__ V, __half* __restrict__ O,
          const float4* __restrict__ wo, const float4* __restrict__ w1,
          const float4* __restrict__ w2, __half2* __restrict__ wdst)
{
    if (blockIdx.x >= 32) {
        // ---- conversion block: 4 independent coalesced float4 per thread ----
        int cid = (blockIdx.x - 32) + CVT2_XBLK * blockIdx.y;   // 0..4607
        int base = cid * 512 + threadIdx.x;
        float4 v[4];
        int gidx[4];
        #pragma unroll
        for (int j = 0; j < 4; j++) {
            int i  = base + j * 128;               // 0 .. 2359295
            int gi = 786432 + i;                   // global float4 index in w-layout
            gidx[j] = gi;
            const float4* s;
            int jj;
            if (gi < 1048576)      { s = wo; jj = gi - 786432; }
            else if (gi < 2097152) { s = w1; jj = gi - 1048576; }
            else                   { s = w2; jj = gi - 2097152; }
            v[j] = s[jj];
        }
        #pragma unroll
        for (int j = 0; j < 4; j++) cvt_store(wdst, gidx[j], v[j]);
        return;
    }

    extern __shared__ char smem[];
    uint32_t sb = smem_u32(smem);
    int bh = blockIdx.x;
    int qt = gridDim.y - 1 - blockIdx.y;      // heavy blocks first
    int qb = qt * 64;
    int tid = threadIdx.x, lane = tid & 31, w = tid >> 5;
    int r0 = lane >> 2, qr = lane & 3;
    int l15 = lane & 15, l16 = (lane >> 4) << 4;

    const __half* qg = Q + ((size_t)bh * SEQ + qb) * HD;
    const __half* kg = K + (size_t)bh * SEQ * HD;
    const __half* vg = V + (size_t)bh * SEQ * HD;

    // init V pad (ones column) for both buffers
    {
        int vbuf = tid >> 6, row = tid & 63;
        uint4* pad = (uint4*)(smem + ATT_VS(vbuf) + row * 144 + 128);
        *pad = make_uint4(0x00003C00u, 0u, 0u, 0u);   // {1.0h, 0, ...}
    }

    // stage Q tile + K/V tile 0
    #pragma unroll
    for (int i = 0; i < 4; i++) {
        int idx = tid + (i << 7);
        int row = idx >> 3, c = idx & 7;
        cp_async16(sb + ATT_QS + sw128(row * 128 + c * 16), qg + row * 64 + c * 8);
    }
    #pragma unroll
    for (int i = 0; i < 4; i++) {
        int idx = tid + (i << 7);
        int row = idx >> 3, c = idx & 7;
        cp_async16(sb + ATT_KS(0) + sw128(row * 128 + c * 16), kg + row * 64 + c * 8);
        cp_async16(sb + ATT_VS(0) + row * 144 + c * 16,        vg + row * 64 + c * 8);
    }
    CP_COMMIT();

    float o[8][4];
    #pragma unroll
    for (int nt = 0; nt < 8; nt++)
        #pragma unroll
        for (int j = 0; j < 4; j++) o[nt][j] = 0.f;
    float ol[4] = {0.f, 0.f, 0.f, 0.f};    // ones-column accumulator (row sums)
    float m0 = -INFINITY, m1 = -INFINITY;

    int ra = w * 16 + r0;
    int rq0 = qb + ra, rq1 = rq0 + 8;
    int ntile = qt + 1;

    for (int t = 0; t < ntile; t++) {
        int buf = t & 1;
        if (t + 1 < ntile) {
            int tn = (t + 1) * 64;
            #pragma unroll
            for (int i = 0; i < 4; i++) {
                int idx = tid + (i << 7);
                int row = idx >> 3, c = idx & 7;
                cp_async16(sb + ATT_KS(buf ^ 1) + sw128(row * 128 + c * 16),
                           kg + (size_t)(tn + row) * 64 + c * 8);
                cp_async16(sb + ATT_VS(buf ^ 1) + row * 144 + c * 16,
                           vg + (size_t)(tn + row) * 64 + c * 8);
            }
            CP_COMMIT();
            CP_WAIT(1);
        } else {
            CP_WAIT(0);
        }
        __syncthreads();

        uint32_t Qs = sb + ATT_QS;
        uint32_t Ks = sb + ATT_KS(buf);
        uint32_t Vs = sb + ATT_VS(buf);

        // ---- S = (Q * 0.125*log2e) @ K^T  -> scores in log2 domain ----
        float s[8][4];
        #pragma unroll
        for (int nt = 0; nt < 8; nt++)
            #pragma unroll
            for (int j = 0; j < 4; j++) s[nt][j] = 0.f;

        #pragma unroll
        for (int kk = 0; kk < 64; kk += 16) {
            uint32_t a[4];
            ldsm4(a, Qs + sw128((uint32_t)((w * 16 + l15) * 128 + kk * 2 + l16)));
            #pragma unroll
            for (int p = 0; p < 4; p++) {
                uint32_t bb[4];
                ldsm4(bb, Ks + sw128((uint32_t)((p * 16 + l15) * 128 + kk * 2 + l16)));
                mma_f16(s[2 * p],     a, bb[0], bb[2]);
                mma_f16(s[2 * p + 1], a, bb[1], bb[3]);
            }
        }

        // ---- mask (diag tile), running max ----
        int t0 = t * 64;
        bool diag = (t == qt);
        float tm0 = -INFINITY, tm1 = -INFINITY;
        #pragma unroll
        for (int nt = 0; nt < 8; nt++) {
            int c = t0 + nt * 8 + (qr << 1);
            if (diag) {
                if (c     > rq0) s[nt][0] = -INFINITY;
                if (c + 1 > rq0) s[nt][1] = -INFINITY;
                if (c     > rq1) s[nt][2] = -INFINITY;
                if (c + 1 > rq1) s[nt][3] = -INFINITY;
            }
            tm0 = fmaxf(tm0, fmaxf(s[nt][0], s[nt][1]));
            tm1 = fmaxf(tm1, fmaxf(s[nt][2], s[nt][3]));
        }
        tm0 = fmaxf(tm0, __shfl_xor_sync(0xffffffffu, tm0, 1));
        tm0 = fmaxf(tm0, __shfl_xor_sync(0xffffffffu, tm0, 2));
        tm1 = fmaxf(tm1, __shfl_xor_sync(0xffffffffu, tm1, 1));
        tm1 = fmaxf(tm1, __shfl_xor_sync(0xffffffffu, tm1, 2));

        float mn0 = fmaxf(m0, tm0), mn1 = fmaxf(m1, tm1);
        float al0 = exp2f(m0 - mn0), al1 = exp2f(m1 - mn1);
        m0 = mn0; m1 = mn1;

        // ---- P = exp2(S - m) via f16x2 MUFU, results are PV a-frags ----
        uint32_t pf[16];
        #pragma unroll
        for (int nt = 0; nt < 8; nt++) {
            pf[2 * nt]     = h2exp2(pack_h2(s[nt][0] - mn0, s[nt][1] - mn0));
            pf[2 * nt + 1] = h2exp2(pack_h2(s[nt][2] - mn1, s[nt][3] - mn1));
        }

        #pragma unroll
        for (int nt = 0; nt < 8; nt++) {
            o[nt][0] *= al0; o[nt][1] *= al0;
            o[nt][2] *= al1; o[nt][3] *= al1;
        }
        ol[0] *= al0; ol[1] *= al0; ol[2] *= al1; ol[3] *= al1;

        // ---- O += P @ [V | 1] ----
        #pragma unroll
        for (int i = 0; i < 4; i++) {
            const uint32_t* a = &pf[4 * i];
            #pragma unroll
            for (int p = 0; p < 4; p++) {
                uint32_t bb[4];
                ldsm4t(bb, Vs + (uint32_t)((16 * i + l15) * 144 + p * 32 + l16));
                mma_f16(o[2 * p],     a, bb[0], bb[1]);
                mma_f16(o[2 * p + 1], a, bb[2], bb[3]);
            }
            uint32_t bl[2];
            ldsm2t(bl, Vs + (uint32_t)((16 * i + l15) * 144 + 128));
            mma_f16(ol, a, bl[0], bl[1]);
        }
        __syncthreads();
    }

    // ---- epilogue ----
    float l0 = __shfl_sync(0xffffffffu, ol[0], lane & ~3);
    float l1 = __shfl_sync(0xffffffffu, ol[2], lane & ~3);
    float i0 = 1.0f / l0, i1 = 1.0f / l1;
    int b = bh >> 4, h = bh & 15;
    int q0 = qb + ra;
    __half* op0 = O + ((size_t)(b * SEQ + q0)) * DIM + h * 64;
    __half* op1 = op0 + 8 * DIM;
    #pragma unroll
    for (int nt = 0; nt < 8; nt++) {
        int c = nt * 8 + (qr << 1);
        *(__half2*)(op0 + c) = __floats2half2_rn(o[nt][0] * i0, o[nt][1] * i0);
        *(__half2*)(op1 + c) = __floats2half2_rn(o[nt][2] * i1, o[nt][3] * i1);
    }
}

// ---------------- launcher ----------------
extern "C" void kernel_launch(void* const* d_in, const int* in_sizes, int n_in,
                              void* d_out, int out_size)
{
    const float* x     = (const float*)d_in[0];
    const float* ln1_s = (const float*)d_in[1];
    const float* ln1_b = (const float*)d_in[2];
    const float* wq    = (const float*)d_in[3];
    const float* wk    = (const float*)d_in[4];
    const float* wv    = (const float*)d_in[5];
    const float* w_out = (const float*)d_in[6];
    const float* b_out = (const float*)d_in[7];
    const float* ln2_s = (const float*)d_in[8];
    const float* ln2_b = (const float*)d_in[9];
    const float* w1    = (const float*)d_in[10];
    const float* b1    = (const float*)d_in[11];
    const float* w2    = (const float*)d_in[12];
    const float* b2    = (const float*)d_in[13];
    float* out = (float*)d_out;

    __half *xn, *q, *k, *v, *ctx, *xn2, *h1, *wh;
    float *res1;
    cudaGetSymbolAddress((void**)&xn,   g_xn);
    cudaGetSymbolAddress((void**)&q,    g_q);
    cudaGetSymbolAddress((void**)&k,    g_k);
    cudaGetSymbolAddress((void**)&v,    g_v);
    cudaGetSymbolAddress((void**)&ctx,  g_ctx);
    cudaGetSymbolAddress((void**)&res1, g_res1);
    cudaGetSymbolAddress((void**)&xn2,  g_xn2);
    cudaGetSymbolAddress((void**)&h1,   g_h1);
    cudaGetSymbolAddress((void**)&wh,   g_wh);

    __half* wqkv_h = wh;
    __half* wo_h   = wh + 3 * 1048576;
    __half* w1_h   = wh + 4 * 1048576;
    __half* w2_h   = wh + 8 * 1048576;

    cudaFuncSetAttribute(mma_gemm<EPI_BIASRES>, cudaFuncAttributeMaxDynamicSharedMemorySize, SM_BYTES);
    cudaFuncSetAttribute(mma_gemm<EPI_GELU>,    cudaFuncAttributeMaxDynamicSharedMemorySize, SM_BYTES);
    cudaFuncSetAttribute(mma_gemm_qkv,          cudaFuncAttributeMaxDynamicSharedMemorySize, SM_BYTES);
    cudaFuncSetAttribute(fa_kernel,             cudaFuncAttributeMaxDynamicSharedMemorySize, ATT_BYTES);

    // 1) cvt wq/wk/wv (ILP4) + LN1 in one launch
    cvt_qkv_ln<<<CVT1_BLOCKS + NTOK, 256>>>((const float4*)wq, (const float4*)wk,
                                            (const float4*)wv, (__half2*)wh,
                                            x, ln1_s, ln1_b, xn);

    // 2) fused QKV projection
    dim3 gqkv(24, NTOK / 128);
    mma_gemm_qkv<<<gqkv, 256, SM_BYTES>>>(xn, wqkv_h, q, k, v);

    // 3) flash attention + hidden wo/w1/w2 conversion
    dim3 gattn(32 + CVT2_XBLK, SEQ / 64);
    fa_kernel<<<gattn, 128, ATT_BYTES>>>(q, k, v, ctx,
                                         (const float4*)w_out, (const float4*)w1,
                                         (const float4*)w2, (__half2*)wh);

    // 4) out projection + bias + residual(x) -> fp32
    dim3 gproj(DIM / 128, NTOK / 128);
    mma_gemm<EPI_BIASRES><<<gproj, 256, SM_BYTES>>>(ctx, wo_h, b_out, x, res1, NTOK, DIM, DIM);

    // 5) LN2 -> fp16
    ln_kernel<<<NTOK, 256>>>(res1, ln2_s, ln2_b, xn2);

    // 6) MLP up + GELU -> fp16
    dim3 gup(FF / 128, NTOK / 128);
    mma_gemm<EPI_GELU><<<gup, 256, SM_BYTES>>>(xn2, w1_h, b1, nullptr, h1, NTOK, FF, DIM);

    // 7) MLP down + bias + residual(res1) -> fp32 out
    mma_gemm<EPI_BIASRES><<<gproj, 256, SM_BYTES>>>(h1, w2_h, b2, res1, out, NTOK, DIM, FF);
}